// round 6
// baseline (speedup 1.0000x reference)
#include <cuda_runtime.h>
#include <math.h>
#include <stdint.h>

// ---- problem constants ----
#define NWIN 98
#define NH 3
#define HD 32
#define CD 96
#define DD 16
#define HH 112
#define WW2 112
#define NWX 2048
#define BATCH 2
#define BTOT (BATCH*NWX)      // 4096
#define MTOT (BTOT*NWIN)      // 401408
#define LTOT (DD*HH*WW2)      // 200704
#define SCALE 0.17677669529663689f
#define VTP 104               // g_vT token pitch (98 used, 104 padded, /4 aligned)

// ---- scratch ----
__device__ unsigned g_q[(size_t)BTOT*NH*NWIN*HD];     // tf32 bits, (b_,h,n,hd), pre-scaled
__device__ unsigned g_k[(size_t)BTOT*NH*NWIN*HD];     // tf32 bits
__device__ unsigned g_vT[(size_t)BTOT*NH*HD*VTP];     // tf32 bits, transposed (dim, token)
__device__ unsigned g_ao[(size_t)MTOT*CD];            // tf32 bits
__device__ unsigned g_y[(size_t)MTOT*CD];             // tf32 bits (scattered spatial)
__device__ float g_bm[8*NH*NWIN*NWIN];                // bias+mask per (class, head)
__device__ unsigned g_Bp[5*9216];                     // prepacked B frags

// ---- tf32 helpers ----
__device__ __forceinline__ unsigned f2tf(float x) {
    unsigned r;
    asm("cvt.rna.tf32.f32 %0, %1;" : "=r"(r) : "f"(x));
    return r;
}
__device__ __forceinline__ void mma_tf32(float* d, uint4 a, uint2 b) {
    asm volatile(
        "mma.sync.aligned.m16n8k8.row.col.f32.tf32.tf32.f32 "
        "{%0,%1,%2,%3}, {%4,%5,%6,%7}, {%8,%9}, {%0,%1,%2,%3};"
        : "+f"(d[0]), "+f"(d[1]), "+f"(d[2]), "+f"(d[3])
        : "r"(a.x), "r"(a.y), "r"(a.z), "r"(a.w), "r"(b.x), "r"(b.y));
}

// ============ K0a: combined bias+mask table ============
__global__ void bm_kernel(const float* __restrict__ table,
                          const float* __restrict__ mask) {
    int idx = blockIdx.x * blockDim.x + threadIdx.x;
    if (idx >= 8 * NH * NWIN * NWIN) return;
    int cls = idx / (NH * NWIN * NWIN);
    int rem = idx % (NH * NWIN * NWIN);
    int head = rem / (NWIN * NWIN);
    int r = rem % (NWIN * NWIN);
    int n = r / NWIN, m = r % NWIN;
    int d1 = n / 49, h1 = (n % 49) / 7, w1 = n % 7;
    int d2 = m / 49, h2 = (m % 49) / 7, w2 = m % 7;
    int t = (d1 - d2 + 1) * 169 + (h1 - h2 + 6) * 13 + (w1 - w2 + 6);
    int wd = (cls & 4) ? 7 : 0;
    int wh = (cls & 2) ? 15 : 0;
    int ww = (cls & 1) ? 15 : 0;
    int widx = wd * 256 + wh * 16 + ww;
    g_bm[idx] = table[t * NH + head] + mask[(size_t)widx * (NWIN * NWIN) + r];
}

// ============ K0b: prepack weights into MMA B-fragment layout ============
__global__ void prepack_kernel(const float* __restrict__ qkvw,
                               const float* __restrict__ projw,
                               const float* __restrict__ fc1w) {
    int idx = blockIdx.x * blockDim.x + threadIdx.x;
    if (idx >= 5 * 9216) return;
    int mat = idx / 9216, rem = idx % 9216;
    int c = rem / 96, k = rem % 96;
    float v;
    if (mat < 3) v = qkvw[(size_t)(mat * 96 + c) * 96 + k];
    else if (mat == 3) v = projw[(size_t)c * 96 + k];
    else v = fc1w[(size_t)c * 96 + k];
    int word = (((c >> 3) * 12 + (k >> 3)) * 32 + (c & 7) * 4 + (k & 3)) * 2 + ((k >> 2) & 1);
    g_Bp[mat * 9216 + word] = f2tf(v);
}

// ============ GEMM common ============
#define GEMM_SMEM ((12800 + 9216) * 4)

__device__ __forceinline__ void mma12(float d[12][4], const unsigned* sAu,
                                      const unsigned* sB, int r0, int tig, int lane) {
    const uint2* b2 = (const uint2*)sB;
    #pragma unroll
    for (int kt = 0; kt < 12; kt++) {
        uint4 af;
        af.x = sAu[r0 * 100 + kt * 8 + tig];
        af.y = sAu[(r0 + 8) * 100 + kt * 8 + tig];
        af.z = sAu[r0 * 100 + kt * 8 + tig + 4];
        af.w = sAu[(r0 + 8) * 100 + kt * 8 + tig + 4];
        #pragma unroll
        for (int nt = 0; nt < 12; nt++) {
            uint2 bf = b2[(nt * 12 + kt) * 32 + lane];
            mma_tf32(d[nt], af, bf);
        }
    }
}

// ============ K1: fused LayerNorm + window-partition + QKV GEMM ============
__global__ __launch_bounds__(256, 2)
void gemm_qkv(const float* __restrict__ x,
              const float* __restrict__ nw,
              const float* __restrict__ nb,
              const float* __restrict__ bias) {
    extern __shared__ unsigned smu[];
    unsigned* sAu = smu;          // [128][100] tf32 bits
    unsigned* sB  = smu + 12800;
    int rowbase = blockIdx.x * 128;
    int tid = threadIdx.x;
    int w = tid >> 5, lane = tid & 31;
    int g = lane >> 2, tig = lane & 3;

    float nw0 = nw[lane], nw1 = nw[lane + 32], nw2 = nw[lane + 64];
    float nb0 = nb[lane], nb1 = nb[lane + 32], nb2 = nb[lane + 64];

    // ---- phase A: gather (shift+window) + LayerNorm -> sAu ----
    for (int i = 0; i < 16; i++) {
        int r = w * 16 + i;
        int m = rowbase + r;
        int b_ = m / NWIN, n = m % NWIN;
        int b = b_ >> 11;
        int widx = b_ & (NWX - 1);
        int wd = widx >> 8, wh = (widx >> 4) & 15, ww = widx & 15;
        int nd = n / 49, nr = n % 49, nh2 = nr / 7, nw2i = nr % 7;
        int dp = wd * 2 + nd, hp = wh * 7 + nh2, wp = ww * 7 + nw2i;
        int d = dp + 1; if (d >= DD) d -= DD;
        int h = hp + 3; if (h >= HH) h -= HH;
        int wq = wp + 3; if (wq >= WW2) wq -= WW2;
        size_t src = ((size_t)b * LTOT + (size_t)(d * (HH * WW2) + h * WW2 + wq)) * CD;
        float v0 = x[src + lane], v1 = x[src + 32 + lane], v2 = x[src + 64 + lane];
        float s = v0 + v1 + v2;
        float ss = v0 * v0 + v1 * v1 + v2 * v2;
        #pragma unroll
        for (int o = 16; o; o >>= 1) {
            s  += __shfl_xor_sync(0xffffffffu, s, o);
            ss += __shfl_xor_sync(0xffffffffu, ss, o);
        }
        float mean = s * (1.0f / 96.0f);
        float var = ss * (1.0f / 96.0f) - mean * mean;
        float rs = rsqrtf(var + 1e-5f);
        sAu[r * 100 + lane]      = f2tf((v0 - mean) * rs * nw0 + nb0);
        sAu[r * 100 + lane + 32] = f2tf((v1 - mean) * rs * nw1 + nb1);
        sAu[r * 100 + lane + 64] = f2tf((v2 - mean) * rs * nw2 + nb2);
    }

    int m0 = rowbase + w * 16 + g;
    int b0 = m0 / NWIN, n0 = m0 % NWIN;
    int b1 = (m0 + 8) / NWIN, n1 = (m0 + 8) % NWIN;
    int r0 = w * 16 + g;
    __syncthreads();

    // ---- phase B: loop q/k/v weight parts ----
    for (int p = 0; p < 3; p++) {
        if (p > 0) __syncthreads();
        {
            const uint4* s4 = (const uint4*)(g_Bp + p * 9216);
            uint4* d4 = (uint4*)sB;
            #pragma unroll
            for (int i = 0; i < 9; i++) d4[tid + i * 256] = s4[tid + i * 256];
        }
        __syncthreads();
        float d[12][4];
        #pragma unroll
        for (int nt = 0; nt < 12; nt++)
            #pragma unroll
            for (int r = 0; r < 4; r++) d[nt][r] = 0.0f;
        mma12(d, sAu, sB, r0, tig, lane);

        if (p < 2) {
            unsigned* dstbuf = (p == 0) ? g_q : g_k;
            float sc = (p == 0) ? SCALE : 1.0f;
            #pragma unroll
            for (int nt = 0; nt < 12; nt++) {
                int c = nt * 8 + tig * 2;
                int head = c >> 5, wd = c & 31;
                float bx = bias[p * 96 + c], by = bias[p * 96 + c + 1];
                uint2 u0 = make_uint2(f2tf((d[nt][0] + bx) * sc), f2tf((d[nt][1] + by) * sc));
                uint2 u1 = make_uint2(f2tf((d[nt][2] + bx) * sc), f2tf((d[nt][3] + by) * sc));
                *(uint2*)(dstbuf + ((((size_t)b0 * NH + head) * NWIN + n0) * HD + wd)) = u0;
                *(uint2*)(dstbuf + ((((size_t)b1 * NH + head) * NWIN + n1) * HD + wd)) = u1;
            }
        } else {
            // v: transposed store (dim-major, token pitch VTP)
            #pragma unroll
            for (int nt = 0; nt < 12; nt++) {
                int c = nt * 8 + tig * 2;
                int head = c >> 5, dim = c & 31;
                float bx = bias[2 * 96 + c], by = bias[2 * 96 + c + 1];
                size_t base0 = (((size_t)b0 * NH + head) * HD + dim) * VTP;
                size_t base1 = (((size_t)b1 * NH + head) * HD + dim) * VTP;
                g_vT[base0 + n0]       = f2tf(d[nt][0] + bx);
                g_vT[base0 + VTP + n0] = f2tf(d[nt][1] + by);
                g_vT[base1 + n1]       = f2tf(d[nt][2] + bx);
                g_vT[base1 + VTP + n1] = f2tf(d[nt][3] + by);
            }
        }
    }
}

// ============ proj / fc1 GEMM ============
template<int EPI>
__global__ __launch_bounds__(256, 2)
void gemm_tc(const float* __restrict__ bias,
             const float* __restrict__ resid,
             float* __restrict__ out) {
    extern __shared__ unsigned smu[];
    unsigned* sAu = smu;
    unsigned* sB  = smu + 12800;
    const unsigned* A = (EPI == 1) ? g_ao : g_y;
    int rowbase = blockIdx.x * 128;
    int tid = threadIdx.x;
    int w = tid >> 5, lane = tid & 31;
    int g = lane >> 2, tig = lane & 3;
    int r0 = w * 16 + g;

    // ---- stage A: direct uint4 copy (already tf32 bits) ----
    {
        const uint4* A4 = (const uint4*)(A + (size_t)rowbase * 96);
        #pragma unroll
        for (int it = 0; it < 12; it++) {
            int idx = tid + it * 256;   // 3072
            int r = idx / 24, k4 = idx % 24;
            *(uint4*)(sAu + r * 100 + k4 * 4) = A4[idx];
        }
    }
    // ---- stage B: copy prepacked frags ----
    {
        const uint4* s4 = (const uint4*)(g_Bp + (EPI == 1 ? 3 : 4) * 9216);
        uint4* d4 = (uint4*)sB;
        #pragma unroll
        for (int i = 0; i < 9; i++) d4[tid + i * 256] = s4[tid + i * 256];
    }
    __syncthreads();

    float d[12][4];
    #pragma unroll
    for (int nt = 0; nt < 12; nt++)
        #pragma unroll
        for (int r = 0; r < 4; r++) d[nt][r] = 0.0f;
    mma12(d, sAu, sB, r0, tig, lane);

    if (EPI == 1) {
        size_t rowdst[2];
        #pragma unroll
        for (int rr = 0; rr < 2; rr++) {
            int m = rowbase + r0 + rr * 8;
            int b_ = m / NWIN, n = m % NWIN;
            int b = b_ >> 11;
            int widx = b_ & (NWX - 1);
            int wd = widx >> 8, wh = (widx >> 4) & 15, ww = widx & 15;
            int nd = n / 49, nr = n % 49, nh2 = nr / 7, nw2 = nr % 7;
            int dp = wd * 2 + nd, hp = wh * 7 + nh2, wp = ww * 7 + nw2;
            int dd = dp + 1; if (dd >= DD) dd -= DD;
            int hh = hp + 3; if (hh >= HH) hh -= HH;
            int ww3 = wp + 3; if (ww3 >= WW2) ww3 -= WW2;
            rowdst[rr] = ((size_t)b * LTOT +
                          (size_t)(dd * (HH * WW2) + hh * WW2 + ww3)) * CD;
        }
        #pragma unroll
        for (int nt = 0; nt < 12; nt++) {
            int c = nt * 8 + tig * 2;
            float bx = bias[c], by = bias[c + 1];
            *(uint2*)(g_y + rowdst[0] + c) =
                make_uint2(f2tf(d[nt][0] + bx), f2tf(d[nt][1] + by));
            *(uint2*)(g_y + rowdst[1] + c) =
                make_uint2(f2tf(d[nt][2] + bx), f2tf(d[nt][3] + by));
        }
    } else {
        int m0 = rowbase + r0;
        #pragma unroll
        for (int nt = 0; nt < 12; nt++) {
            int c = nt * 8 + tig * 2;
            float bx = bias[c], by = bias[c + 1];
            #pragma unroll
            for (int rr = 0; rr < 2; rr++) {
                size_t o = (size_t)(m0 + rr * 8) * CD + c;
                float v0 = d[nt][rr * 2] + bx;
                float v1 = d[nt][rr * 2 + 1] + by;
                float g0 = 0.5f * v0 * (1.0f + erff(v0 * 0.70710678118654752f));
                float g1 = 0.5f * v1 * (1.0f + erff(v1 * 0.70710678118654752f));
                float2 rv = *(const float2*)(resid + o);
                *(float2*)(out + o) = make_float2(rv.x + g0, rv.y + g1);
            }
        }
    }
}

// ============ K3: tensor-core window attention ============
// smem (u32 words):
//   q_u [112][36] = 4032  @ 0
//   k_u [104][36] = 3744  @ 4032
//   Ss  [98][108] = 10584 @ 0   (float, overlays q_u/k_u after S phase)
//   vT  [32][108] = 3456  @ 10584
// total = 14040 words = 56160 B -> 4 CTAs/SM
#define ATTN_SMEM (14040 * 4)
__global__ __launch_bounds__(224, 4)
void attn_kernel() {
    extern __shared__ unsigned smu[];
    unsigned* q_u = smu;
    unsigned* k_u = smu + 4032;
    float* Ss = (float*)smu;
    unsigned* vT = smu + 10584;

    int b_ = blockIdx.x;
    int head = blockIdx.y;
    int tid = threadIdx.x;
    int w = tid >> 5, lane = tid & 31;
    int g = lane >> 2, tig = lane & 3;
    size_t bh = (size_t)b_ * NH + head;

    // ---- load q/k (uint4, no cvt) ----
    {
        const uint4* q4 = (const uint4*)(g_q + bh * (NWIN * HD));
        const uint4* k4 = (const uint4*)(g_k + bh * (NWIN * HD));
        for (int i4 = tid; i4 < 784; i4 += 224) {
            int n = i4 >> 3;
            int c = (i4 & 7) << 2;
            *(uint4*)(q_u + n * 36 + c) = q4[i4];
            *(uint4*)(k_u + n * 36 + c) = k4[i4];
        }
        // v: rows pre-transposed in global (pitch VTP=104, tail zero-padded)
        const uint4* v4 = (const uint4*)(g_vT + bh * (HD * VTP));
        for (int i4 = tid; i4 < 832; i4 += 224) {
            int dim = i4 / 26;
            int t4 = (i4 % 26) << 2;
            *(uint4*)(vT + dim * 108 + t4) = v4[i4];
        }
    }
    __syncthreads();

    int r0 = w * 16 + g;
    // ---- S = Q K^T ----
    float d[13][4];
    #pragma unroll
    for (int nt = 0; nt < 13; nt++)
        #pragma unroll
        for (int r = 0; r < 4; r++) d[nt][r] = 0.0f;
    {
        uint4 af[4];
        #pragma unroll
        for (int kt = 0; kt < 4; kt++) {
            af[kt].x = q_u[r0 * 36 + kt * 8 + tig];
            af[kt].y = q_u[(r0 + 8) * 36 + kt * 8 + tig];
            af[kt].z = q_u[r0 * 36 + kt * 8 + tig + 4];
            af[kt].w = q_u[(r0 + 8) * 36 + kt * 8 + tig + 4];
        }
        #pragma unroll
        for (int nt = 0; nt < 13; nt++) {
            #pragma unroll
            for (int kt = 0; kt < 4; kt++) {
                uint2 bf;
                bf.x = k_u[(nt * 8 + g) * 36 + kt * 8 + tig];
                bf.y = k_u[(nt * 8 + g) * 36 + kt * 8 + tig + 4];
                mma_tf32(d[nt], af[kt], bf);
            }
        }
    }
    __syncthreads();   // q/k reads done; region becomes Ss

    bool v0 = r0 < 98, v1 = (r0 + 8) < 98;
    // ---- bias/mask + exp + row-sum in registers ----
    {
        int widx = b_ & (NWX - 1);
        int cls = (((widx >> 8) == 7) << 2) | ((((widx >> 4) & 15) == 15) << 1) |
                  ((widx & 15) == 15);
        const float* bmp = g_bm + (size_t)(cls * NH + head) * (NWIN * NWIN);
        float s0 = 0.0f, s1 = 0.0f;
        #pragma unroll
        for (int nt = 0; nt < 13; nt++) {
            int c0 = nt * 8 + tig * 2;
            float e0 = 0.f, e1 = 0.f, e2 = 0.f, e3 = 0.f;
            if (c0 < 98) {
                if (v0) {
                    float2 bb = __ldg((const float2*)(bmp + r0 * 98 + c0));
                    e0 = __expf(d[nt][0] + bb.x);
                    e1 = __expf(d[nt][1] + bb.y);
                }
                if (v1) {
                    float2 bb = __ldg((const float2*)(bmp + (r0 + 8) * 98 + c0));
                    e2 = __expf(d[nt][2] + bb.x);
                    e3 = __expf(d[nt][3] + bb.y);
                }
            }
            d[nt][0] = e0; d[nt][1] = e1; d[nt][2] = e2; d[nt][3] = e3;
            s0 += e0 + e1; s1 += e2 + e3;
        }
        s0 += __shfl_xor_sync(0xffffffffu, s0, 1);
        s0 += __shfl_xor_sync(0xffffffffu, s0, 2);
        s1 += __shfl_xor_sync(0xffffffffu, s1, 1);
        s1 += __shfl_xor_sync(0xffffffffu, s1, 2);
        float i0 = v0 ? (1.0f / s0) : 0.0f;
        float i1 = v1 ? (1.0f / s1) : 0.0f;
        #pragma unroll
        for (int nt = 0; nt < 13; nt++) {
            int c0 = nt * 8 + tig * 2;
            if (v0) *(float2*)(Ss + r0 * 108 + c0) =
                make_float2(d[nt][0] * i0, d[nt][1] * i0);
            if (v1) *(float2*)(Ss + (r0 + 8) * 108 + c0) =
                make_float2(d[nt][2] * i1, d[nt][3] * i1);
        }
    }
    __syncthreads();

    // ---- O = P V ----
    {
        int rA = v0 ? r0 : 0;
        int rB = v1 ? (r0 + 8) : 0;
        unsigned mA = v0 ? 0xffffffffu : 0u;
        unsigned mB = v1 ? 0xffffffffu : 0u;
        float o[4][4];
        #pragma unroll
        for (int nt = 0; nt < 4; nt++)
            #pragma unroll
            for (int r = 0; r < 4; r++) o[nt][r] = 0.0f;
        #pragma unroll
        for (int kt = 0; kt < 13; kt++) {
            uint4 af;
            af.x = f2tf(Ss[rA * 108 + kt * 8 + tig]) & mA;
            af.y = f2tf(Ss[rB * 108 + kt * 8 + tig]) & mB;
            af.z = f2tf(Ss[rA * 108 + kt * 8 + tig + 4]) & mA;
            af.w = f2tf(Ss[rB * 108 + kt * 8 + tig + 4]) & mB;
            #pragma unroll
            for (int nt = 0; nt < 4; nt++) {
                uint2 bf;
                bf.x = vT[(nt * 8 + g) * 108 + kt * 8 + tig];
                bf.y = vT[(nt * 8 + g) * 108 + kt * 8 + tig + 4];
                mma_tf32(o[nt], af, bf);
            }
        }
        #pragma unroll
        for (int nt = 0; nt < 4; nt++) {
            int c = nt * 8 + tig * 2;
            if (v0)
                *(uint2*)(g_ao + ((size_t)b_ * NWIN + r0) * CD + head * HD + c) =
                    make_uint2(f2tf(o[nt][0]), f2tf(o[nt][1]));
            if (v1)
                *(uint2*)(g_ao + ((size_t)b_ * NWIN + r0 + 8) * CD + head * HD + c) =
                    make_uint2(f2tf(o[nt][2]), f2tf(o[nt][3]));
        }
    }
}

// ============ launch ============
extern "C" void kernel_launch(void* const* d_in, const int* in_sizes, int n_in,
                              void* d_out, int out_size) {
    const float* x     = (const float*)d_in[0];
    const float* mask  = (const float*)d_in[1];
    const float* n1w   = (const float*)d_in[2];
    const float* n1b   = (const float*)d_in[3];
    const float* qkvw  = (const float*)d_in[4];
    const float* qkvb  = (const float*)d_in[5];
    const float* relt  = (const float*)d_in[6];
    const float* projw = (const float*)d_in[7];
    const float* projb = (const float*)d_in[8];
    const float* fc1w  = (const float*)d_in[9];
    const float* fc1b  = (const float*)d_in[10];
    float* out = (float*)d_out;

    cudaFuncSetAttribute(attn_kernel, cudaFuncAttributeMaxDynamicSharedMemorySize, ATTN_SMEM);
    cudaFuncSetAttribute(gemm_qkv, cudaFuncAttributeMaxDynamicSharedMemorySize, GEMM_SMEM);
    cudaFuncSetAttribute(gemm_tc<1>, cudaFuncAttributeMaxDynamicSharedMemorySize, GEMM_SMEM);
    cudaFuncSetAttribute(gemm_tc<2>, cudaFuncAttributeMaxDynamicSharedMemorySize, GEMM_SMEM);

    bm_kernel<<<(8 * NH * NWIN * NWIN + 255) / 256, 256>>>(relt, mask);
    prepack_kernel<<<(5 * 9216 + 255) / 256, 256>>>(qkvw, projw, fc1w);
    gemm_qkv<<<MTOT / 128, 256, GEMM_SMEM>>>(x, n1w, n1b, qkvb);
    attn_kernel<<<dim3(BTOT, NH), 224, ATTN_SMEM>>>();
    gemm_tc<1><<<MTOT / 128, 256, GEMM_SMEM>>>(projb, nullptr, nullptr);
    gemm_tc<2><<<MTOT / 128, 256, GEMM_SMEM>>>(fc1b, x, out);
}